// round 14
// baseline (speedup 1.0000x reference)
#include <cuda_runtime.h>
#include <cuda_bf16.h>
#include <math.h>
#include <stdint.h>

#define B_TOTAL 16384
#define F_DIM   512
#define P_DIM   128
#define C_DIM   10

#define BM   128
#define BK   64
#define TPB  512
#define SIP  130          // float pitch of si tile [128 p][130]
#define NKT  (F_DIM / BK) // 8

// ---------------- smem layout (bytes) ----------------
// xh[2 stages] @ 0        (32768)
// xl[2 stages] @ 32768    (32768)
// wh[8 tiles]  @ 65536    (131072)  -- full w resident, converted in prologue
// tables @ 196608
// post-GEMM union @0: si [128 p][130 b] float = 66560 B (overlaps xh/xl + 1KB of wh[0])
#define TSTG    16384
#define OFF_XL  32768
#define OFF_WH  65536
#define OFF_US  196608
#define OFF_WSQ 201728
#define OFF_GAM 202240
#define OFF_ALP 202752
#define OFF_XNS 203264
#define OFF_XNP 203776
#define SMEM_BYTES 205824

// ---------------- helpers ----------------
__device__ __forceinline__ unsigned pk2(float a, float b) {
    __nv_bfloat162 t;
    t.x = __float2bfloat16_rn(a);
    t.y = __float2bfloat16_rn(b);
    return *reinterpret_cast<unsigned*>(&t);
}
__device__ __forceinline__ void ldsm4(unsigned& r0, unsigned& r1, unsigned& r2, unsigned& r3,
                                      unsigned addr) {
    asm volatile("ldmatrix.sync.aligned.m8n8.x4.shared.b16 {%0,%1,%2,%3}, [%4];\n"
                 : "=r"(r0), "=r"(r1), "=r"(r2), "=r"(r3) : "r"(addr));
}
__device__ __forceinline__ void mma16816(float* c, const unsigned* a, const unsigned* b) {
    asm volatile(
        "mma.sync.aligned.m16n8k16.row.col.f32.bf16.bf16.f32 "
        "{%0,%1,%2,%3}, {%4,%5,%6,%7}, {%8,%9}, {%0,%1,%2,%3};\n"
        : "+f"(c[0]), "+f"(c[1]), "+f"(c[2]), "+f"(c[3])
        : "r"(a[0]), "r"(a[1]), "r"(a[2]), "r"(a[3]), "r"(b[0]), "r"(b[1]));
}

__global__ void __launch_bounds__(TPB, 1)
ds_main(const float* __restrict__ x,
        const float* __restrict__ w,
        const float* __restrict__ eta,
        const float* __restrict__ xi,
        const float* __restrict__ beta,
        float* __restrict__ out) {
    extern __shared__ char smem[];
    float* si  = (float*)smem;
    float* us  = (float*)(smem + OFF_US);
    float* wsq = (float*)(smem + OFF_WSQ);
    float* gam = (float*)(smem + OFF_GAM);
    float* alp = (float*)(smem + OFF_ALP);
    float* xns = (float*)(smem + OFF_XNS);
    float* xnp = (float*)(smem + OFF_XNP);
    unsigned sm_u32 = (unsigned)__cvta_generic_to_shared(smem);

    const int tid  = threadIdx.x;
    const int lane = tid & 31;
    const int wid  = tid >> 5;
    const int row0 = blockIdx.x * BM;

    // loader roles: thread owns row lr, quarter kq (16 elems of a 64-col tile)
    const int lr = tid >> 2;       // 0..127
    const int kq = tid & 3;        // 0..3
    const unsigned lmsk = (unsigned)((lr & 7) << 4);

    // ================= PROLOGUE: convert all of w into smem, tables =================
    {
        float wq = 0.f;
        const float* wrow = w + (size_t)lr * F_DIM;
#pragma unroll
        for (int kt = 0; kt < NKT; ++kt) {
            const float* p = wrow + kt * BK + kq * 16;
            float4 wv0 = *(const float4*)(p + 0);
            float4 wv1 = *(const float4*)(p + 4);
            float4 wv2 = *(const float4*)(p + 8);
            float4 wv3 = *(const float4*)(p + 12);
            wq = fmaf(wv0.x, wv0.x, wq); wq = fmaf(wv0.y, wv0.y, wq);
            wq = fmaf(wv0.z, wv0.z, wq); wq = fmaf(wv0.w, wv0.w, wq);
            wq = fmaf(wv1.x, wv1.x, wq); wq = fmaf(wv1.y, wv1.y, wq);
            wq = fmaf(wv1.z, wv1.z, wq); wq = fmaf(wv1.w, wv1.w, wq);
            wq = fmaf(wv2.x, wv2.x, wq); wq = fmaf(wv2.y, wv2.y, wq);
            wq = fmaf(wv2.z, wv2.z, wq); wq = fmaf(wv2.w, wv2.w, wq);
            wq = fmaf(wv3.x, wv3.x, wq); wq = fmaf(wv3.y, wv3.y, wq);
            wq = fmaf(wv3.z, wv3.z, wq); wq = fmaf(wv3.w, wv3.w, wq);
            uint4 hv0, hv1;
            hv0.x = pk2(wv0.x, wv0.y); hv0.y = pk2(wv0.z, wv0.w);
            hv0.z = pk2(wv1.x, wv1.y); hv0.w = pk2(wv1.z, wv1.w);
            hv1.x = pk2(wv2.x, wv2.y); hv1.y = pk2(wv2.z, wv2.w);
            hv1.z = pk2(wv3.x, wv3.y); hv1.w = pk2(wv3.z, wv3.w);
            char* bH = smem + OFF_WH + kt * TSTG + lr * 128;
            *(uint4*)(bH + ((unsigned)((kq * 2 + 0) * 16) ^ lmsk)) = hv0;
            *(uint4*)(bH + ((unsigned)((kq * 2 + 1) * 16) ^ lmsk)) = hv1;
        }
        xnp[tid] = wq;   // wsq partials (4 per row)

        // small tables: one thread per plate p
        if (tid < P_DIM) {
            int p = tid;
            float e = eta[p];
            gam[p] = e * e;
            alp[p] = 1.f / (1.f + expf(-xi[p]));
            float b2[C_DIM];
            float bs = 0.f;
#pragma unroll
            for (int c = 0; c < C_DIM; ++c) {
                float b = beta[c * P_DIM + p];
                b2[c] = b * b;
                bs += b2[c];
            }
            float inv = 1.f / bs;
#pragma unroll
            for (int c = 0; c < C_DIM; ++c) us[c * P_DIM + p] = b2[c] * inv;
        }
    }
    __syncthreads();
    if (tid < P_DIM)
        wsq[tid] = xnp[4 * tid] + xnp[4 * tid + 1] + xnp[4 * tid + 2] + xnp[4 * tid + 3];
    // (wsq read only in epilogue; mainloop syncs cover visibility)

    // ================= MAINLOOP =================
    const float* xblk = x + (size_t)row0 * F_DIM;

    float acc[2][4][4];
#pragma unroll
    for (int mt = 0; mt < 2; ++mt)
#pragma unroll
        for (int nt = 0; nt < 4; ++nt)
#pragma unroll
            for (int e = 0; e < 4; ++e) acc[mt][nt][e] = 0.f;

    float xn = 0.f;
    float4 xv[4];

    auto ldx = [&](int kt) {
        const float* p = xblk + (size_t)lr * F_DIM + kt * BK + kq * 16;
#pragma unroll
        for (int j = 0; j < 4; ++j) xv[j] = *(const float4*)(p + 4 * j);
    };
    auto stx = [&](int s) {
        char* bH = smem + s * TSTG + lr * 128;
        char* bL = smem + OFF_XL + s * TSTG + lr * 128;
#pragma unroll
        for (int j = 0; j < 2; ++j) {
            float f0 = xv[2 * j].x,     f1 = xv[2 * j].y;
            float f2 = xv[2 * j].z,     f3 = xv[2 * j].w;
            float f4 = xv[2 * j + 1].x, f5 = xv[2 * j + 1].y;
            float f6 = xv[2 * j + 1].z, f7 = xv[2 * j + 1].w;
            xn = fmaf(f0, f0, xn); xn = fmaf(f1, f1, xn);
            xn = fmaf(f2, f2, xn); xn = fmaf(f3, f3, xn);
            xn = fmaf(f4, f4, xn); xn = fmaf(f5, f5, xn);
            xn = fmaf(f6, f6, xn); xn = fmaf(f7, f7, xn);
            uint4 hv, lv;
            hv.x = pk2(f0, f1); hv.y = pk2(f2, f3);
            hv.z = pk2(f4, f5); hv.w = pk2(f6, f7);
            __nv_bfloat16 h0 = __float2bfloat16_rn(f0), h1 = __float2bfloat16_rn(f1);
            __nv_bfloat16 h2 = __float2bfloat16_rn(f2), h3 = __float2bfloat16_rn(f3);
            __nv_bfloat16 h4 = __float2bfloat16_rn(f4), h5 = __float2bfloat16_rn(f5);
            __nv_bfloat16 h6 = __float2bfloat16_rn(f6), h7 = __float2bfloat16_rn(f7);
            lv.x = pk2(f0 - __bfloat162float(h0), f1 - __bfloat162float(h1));
            lv.y = pk2(f2 - __bfloat162float(h2), f3 - __bfloat162float(h3));
            lv.z = pk2(f4 - __bfloat162float(h4), f5 - __bfloat162float(h5));
            lv.w = pk2(f6 - __bfloat162float(h6), f7 - __bfloat162float(h7));
            unsigned c = (unsigned)((kq * 2 + j) * 16) ^ lmsk;
            *(uint4*)(bH + c) = hv;
            *(uint4*)(bL + c) = lv;
        }
    };

    // warp tiling: 4x4 warps; warp tile 32 rows x 32 cols
    const int wm = (wid & 3) * 32;
    const int wn = (wid >> 2) * 32;
    const int ai = lane & 7;
    const int ag = lane >> 3;

    unsigned arow[2], amsk[2];
#pragma unroll
    for (int mt = 0; mt < 2; ++mt) {
        int r = wm + mt * 16 + (ag & 1) * 8 + ai;
        arow[mt] = (unsigned)(r * 128);
        amsk[mt] = (unsigned)((r & 7) << 4);
    }
    const unsigned a_c0 = (unsigned)((ag >> 1) * 16);
    unsigned brow[2], bmsk[2];
#pragma unroll
    for (int ntp = 0; ntp < 2; ++ntp) {
        int r = wn + ntp * 16 + (ag >> 1) * 8 + ai;
        brow[ntp] = (unsigned)(r * 128);
        bmsk[ntp] = (unsigned)((r & 7) << 4);
    }
    const unsigned b_c0 = (unsigned)((ag & 1) * 16);

    auto compute = [&](int s, int kt) {
        const unsigned xh_b = sm_u32 + s * TSTG;
        const unsigned xl_b = sm_u32 + OFF_XL + s * TSTG;
        const unsigned wh_b = sm_u32 + OFF_WH + kt * TSTG;
#pragma unroll
        for (int kk = 0; kk < 4; ++kk) {
            const unsigned ca  = a_c0 + kk * 32;
            const unsigned cbb = b_c0 + kk * 32;
            unsigned ah[2][4], al[2][4], bh[4][2];
#pragma unroll
            for (int mt = 0; mt < 2; ++mt)
                ldsm4(ah[mt][0], ah[mt][1], ah[mt][2], ah[mt][3],
                      xh_b + arow[mt] + (ca ^ amsk[mt]));
#pragma unroll
            for (int ntp = 0; ntp < 2; ++ntp)
                ldsm4(bh[2 * ntp][0], bh[2 * ntp][1], bh[2 * ntp + 1][0], bh[2 * ntp + 1][1],
                      wh_b + brow[ntp] + (cbb ^ bmsk[ntp]));
#pragma unroll
            for (int nt = 0; nt < 4; ++nt)
#pragma unroll
                for (int mt = 0; mt < 2; ++mt)
                    mma16816(acc[mt][nt], ah[mt], bh[nt]);
#pragma unroll
            for (int mt = 0; mt < 2; ++mt)
                ldsm4(al[mt][0], al[mt][1], al[mt][2], al[mt][3],
                      xl_b + arow[mt] + (ca ^ amsk[mt]));
#pragma unroll
            for (int nt = 0; nt < 4; ++nt)
#pragma unroll
                for (int mt = 0; mt < 2; ++mt)
                    mma16816(acc[mt][nt], al[mt], bh[nt]);
        }
    };

    // 2-stage x pipeline (w fully resident)
    ldx(0);
    stx(0);
    __syncthreads();       // covers prologue wh + stage-0 x

    for (int kt = 0; kt < NKT; ++kt) {
        int cur = kt & 1;
        if (kt < NKT - 1) ldx(kt + 1);
        compute(cur, kt);
        if (kt < NKT - 1) stx(1 - cur);
        __syncthreads();
    }

    // ---- ||x||^2 reduction (4 partials per row) ----
    xnp[tid] = xn;
    __syncthreads();
    if (tid < BM)
        xns[tid] = xnp[4 * tid] + xnp[4 * tid + 1] + xnp[4 * tid + 2] + xnp[4 * tid + 3];
    __syncthreads();

    // ---- epilogue: d -> si[p][b] ----
    {
        const int lq  = lane >> 2;
        const int lr2 = (lane & 3) * 2;
        float xnv[4];
#pragma unroll
        for (int mt = 0; mt < 2; ++mt) {
            xnv[mt * 2 + 0] = xns[wm + mt * 16 + lq];
            xnv[mt * 2 + 1] = xns[wm + mt * 16 + lq + 8];
        }
#pragma unroll
        for (int nt = 0; nt < 4; ++nt) {
            int cp = wn + nt * 8 + lr2;
            float ws0 = wsq[cp],     ws1 = wsq[cp + 1];
            float ga0 = gam[cp],     ga1 = gam[cp + 1];
            float al0 = alp[cp],     al1 = alp[cp + 1];
#pragma unroll
            for (int mt = 0; mt < 2; ++mt) {
                int r0 = wm + mt * 16 + lq;
                int r1 = r0 + 8;
                const float* a = acc[mt][nt];
                float d00 = xnv[mt * 2]     + ws0 - 2.f * a[0];
                float d01 = xnv[mt * 2]     + ws1 - 2.f * a[1];
                float d10 = xnv[mt * 2 + 1] + ws0 - 2.f * a[2];
                float d11 = xnv[mt * 2 + 1] + ws1 - 2.f * a[3];
                si[cp * SIP + r0]       = al0 * __expf(-ga0 * d00);
                si[(cp + 1) * SIP + r0] = al1 * __expf(-ga1 * d01);
                si[cp * SIP + r1]       = al0 * __expf(-ga0 * d10);
                si[(cp + 1) * SIP + r1] = al1 * __expf(-ga1 * d11);
            }
        }
    }
    __syncthreads();

    // ---- Dempster scan: one thread per batch row ----
    if (tid < BM) {
        const int r = tid;
        float mx = 0.f;
        for (int p = 0; p < P_DIM; ++p) mx = fmaxf(mx, si[p * SIP + r]);
        const float sinv = 1.f / (mx + 1e-4f);

        float s = si[r] * sinv;
        float m[C_DIM];
#pragma unroll
        for (int k = 0; k < C_DIM; ++k) m[k] = us[k * P_DIM + 0] * s;
        float o = 1.f - s;

        for (int p = 1; p < P_DIM; ++p) {
            s = si[p * SIP + r] * sinv;
            float om = 1.f - s;
            float os = o * s;
#pragma unroll
            for (int k = 0; k < C_DIM; ++k) {
                float u = us[k * P_DIM + p];
                float t = fmaf(s, u, om);        // 1 - s + s*u
                m[k] = fmaf(m[k], t, os * u);
            }
            o = 3.f * o * om;                    // c_omega = 3*o1*o2
            if ((p & 7) == 7) {                  // scale-invariant renorm
                float ssum = o;
#pragma unroll
                for (int k = 0; k < C_DIM; ++k) ssum += m[k];
                float rinv = 1.f / ssum;
#pragma unroll
                for (int k = 0; k < C_DIM; ++k) m[k] *= rinv;
                o *= rinv;
            }
        }
        float ssum = o;
#pragma unroll
        for (int k = 0; k < C_DIM; ++k) ssum += m[k];
        float rinv = 1.f / ssum;
        float* op = out + (size_t)(row0 + r) * (C_DIM + 1);
#pragma unroll
        for (int k = 0; k < C_DIM; ++k) op[k] = m[k] * rinv;
        op[C_DIM] = o * rinv;
    }
}

// ---------------- launch ----------------
extern "C" void kernel_launch(void* const* d_in, const int* in_sizes, int n_in,
                              void* d_out, int out_size) {
    const float* x    = (const float*)d_in[0];
    const float* w    = (const float*)d_in[1];
    const float* eta  = (const float*)d_in[2];
    const float* xi   = (const float*)d_in[3];
    const float* beta = (const float*)d_in[4];
    float* out = (float*)d_out;

    cudaFuncSetAttribute(ds_main, cudaFuncAttributeMaxDynamicSharedMemorySize,
                         SMEM_BYTES);
    ds_main<<<B_TOTAL / BM, TPB, SMEM_BYTES>>>(x, w, eta, xi, beta, out);
}

// round 16
// speedup vs baseline: 1.2520x; 1.2520x over previous
#include <cuda_runtime.h>
#include <cuda_bf16.h>
#include <cuda_fp16.h>
#include <math.h>
#include <stdint.h>

#define B_TOTAL 16384
#define F_DIM   512
#define P_DIM   128
#define C_DIM   10

#define BM   128
#define BK   64
#define TPB  512
#define SIP  130          // float pitch of si tile [128 p][130]
#define NKT  (F_DIM / BK) // 8

// ---------------- device-global precomputed tensors ----------------
__device__ __align__(16) __half g_wh[P_DIM * F_DIM];
__device__ float g_wsq[P_DIM];
__device__ float g_gamma[P_DIM];
__device__ float g_alpha[P_DIM];
__device__ float g_u[C_DIM * P_DIM];   // [c][p]

// ---------------- helpers ----------------
__device__ __forceinline__ unsigned pk2h(float a, float b) {
    __half2 t;
    t.x = __float2half_rn(a);
    t.y = __float2half_rn(b);
    return *reinterpret_cast<unsigned*>(&t);
}
__device__ __forceinline__ void cp16(unsigned dst, const void* src) {
    asm volatile("cp.async.ca.shared.global [%0], [%1], 16;\n" :: "r"(dst), "l"(src));
}
__device__ __forceinline__ void cp_commit() { asm volatile("cp.async.commit_group;\n"); }
__device__ __forceinline__ void cp_wait0()  { asm volatile("cp.async.wait_group 0;\n"); }

__device__ __forceinline__ void ldsm4(unsigned& r0, unsigned& r1, unsigned& r2, unsigned& r3,
                                      unsigned addr) {
    asm volatile("ldmatrix.sync.aligned.m8n8.x4.shared.b16 {%0,%1,%2,%3}, [%4];\n"
                 : "=r"(r0), "=r"(r1), "=r"(r2), "=r"(r3) : "r"(addr));
}
__device__ __forceinline__ void mma16816(float* c, const unsigned* a, const unsigned* b) {
    asm volatile(
        "mma.sync.aligned.m16n8k16.row.col.f32.f16.f16.f32 "
        "{%0,%1,%2,%3}, {%4,%5,%6,%7}, {%8,%9}, {%0,%1,%2,%3};\n"
        : "+f"(c[0]), "+f"(c[1]), "+f"(c[2]), "+f"(c[3])
        : "r"(a[0]), "r"(a[1]), "r"(a[2]), "r"(a[3]), "r"(b[0]), "r"(b[1]));
}

// ---------------- fused precompute kernel ----------------
__global__ void ds_precomp(const float* __restrict__ w,
                           const float* __restrict__ eta,
                           const float* __restrict__ xi,
                           const float* __restrict__ beta) {
    if (blockIdx.x < 128) {
        int i = blockIdx.x * 256 + threadIdx.x;
        float2 v = ((const float2*)w)[i];
        ((unsigned*)g_wh)[i] = pk2h(v.x, v.y);
        return;
    }
    int lane = threadIdx.x & 31;
    int p = (blockIdx.x - 128) * 8 + (threadIdx.x >> 5);
    float s = 0.f;
    const float4* wr = (const float4*)(w + (size_t)p * F_DIM);
#pragma unroll
    for (int j = 0; j < 4; ++j) {
        float4 v = wr[j * 32 + lane];
        s = fmaf(v.x, v.x, s);
        s = fmaf(v.y, v.y, s);
        s = fmaf(v.z, v.z, s);
        s = fmaf(v.w, v.w, s);
    }
#pragma unroll
    for (int o = 16; o > 0; o >>= 1) s += __shfl_xor_sync(0xffffffffu, s, o);
    float b2 = 0.f;
    if (lane < C_DIM) {
        float b = beta[lane * P_DIM + p];
        b2 = b * b;
    }
    float bs = b2;
#pragma unroll
    for (int o = 16; o > 0; o >>= 1) bs += __shfl_xor_sync(0xffffffffu, bs, o);
    if (lane < C_DIM) g_u[lane * P_DIM + p] = b2 / bs;
    if (lane == 0) {
        g_wsq[p] = s;
        float e = eta[p];
        g_gamma[p] = e * e;
        g_alpha[p] = 1.f / (1.f + expf(-xi[p]));
    }
}

// ---------------- smem layout (bytes) ----------------
// GEMM phase (SW128 swizzled, 128B rows, tile = 128 rows x 64 fp16 = 16384 B):
//   xh: @0       (+ s*16384, 2 stages)
//   wh: @32768   (+ s*16384, 2 stages)  ends 65536
// post-GEMM union @0: si [128 p][130 b] float = 66560 B
// tail @66560:
#define OFF_WH  32768
#define TSTG    16384
#define OFF_US  66560
#define OFF_WSQ 71680
#define OFF_GAM 72192
#define OFF_ALP 72704
#define OFF_XNS 73216
#define OFF_XNP 73728
#define SMEM_BYTES 75776

__global__ void __launch_bounds__(TPB, 1)
ds_main(const float* __restrict__ x, float* __restrict__ out) {
    extern __shared__ char smem[];
    float* si  = (float*)smem;
    float* us  = (float*)(smem + OFF_US);
    float* wsq = (float*)(smem + OFF_WSQ);
    float* gam = (float*)(smem + OFF_GAM);
    float* alp = (float*)(smem + OFF_ALP);
    float* xns = (float*)(smem + OFF_XNS);
    float* xnp = (float*)(smem + OFF_XNP);
    unsigned sm_u32 = (unsigned)__cvta_generic_to_shared(smem);

    const int tid  = threadIdx.x;
    const int lane = tid & 31;
    const int wid  = tid >> 5;
    const int row0 = blockIdx.x * BM;

    for (int i = tid; i < C_DIM * P_DIM; i += TPB) us[i] = g_u[i];
    if (tid < P_DIM) {
        wsq[tid] = g_wsq[tid];
        gam[tid] = g_gamma[tid];
        alp[tid] = g_alpha[tid];
    }

    // loader roles: thread owns row lr, quarter kq (16 elems of BK=64)
    const int lr = tid >> 2;       // 0..127
    const int kq = tid & 3;        // 0..3
    const unsigned lmsk = (unsigned)((lr & 7) << 4);
    const float* xblk = x + (size_t)row0 * F_DIM;

    float acc[2][4][4];
#pragma unroll
    for (int mt = 0; mt < 2; ++mt)
#pragma unroll
        for (int nt = 0; nt < 4; ++nt)
#pragma unroll
            for (int e = 0; e < 4; ++e) acc[mt][nt][e] = 0.f;

    float xn = 0.f;
    float4 xv[4];

    auto cp_w = [&](int kt, int s) {
        const __half* sH = g_wh + (size_t)lr * F_DIM + kt * BK + kq * 16;
        unsigned bH = sm_u32 + OFF_WH + s * TSTG + lr * 128;
#pragma unroll
        for (int j = 0; j < 2; ++j) {
            unsigned c = (unsigned)((kq * 2 + j) * 16) ^ lmsk;
            cp16(bH + c, sH + 8 * j);
        }
        cp_commit();
    };
    auto ldx = [&](int kt) {
        const float* p = xblk + (size_t)lr * F_DIM + kt * BK + kq * 16;
#pragma unroll
        for (int j = 0; j < 4; ++j) xv[j] = *(const float4*)(p + 4 * j);
    };
    auto stx = [&](int s) {
        char* bH = smem + s * TSTG + lr * 128;
#pragma unroll
        for (int j = 0; j < 2; ++j) {
            float f0 = xv[2 * j].x,     f1 = xv[2 * j].y;
            float f2 = xv[2 * j].z,     f3 = xv[2 * j].w;
            float f4 = xv[2 * j + 1].x, f5 = xv[2 * j + 1].y;
            float f6 = xv[2 * j + 1].z, f7 = xv[2 * j + 1].w;
            xn = fmaf(f0, f0, xn); xn = fmaf(f1, f1, xn);
            xn = fmaf(f2, f2, xn); xn = fmaf(f3, f3, xn);
            xn = fmaf(f4, f4, xn); xn = fmaf(f5, f5, xn);
            xn = fmaf(f6, f6, xn); xn = fmaf(f7, f7, xn);
            uint4 hv;
            hv.x = pk2h(f0, f1); hv.y = pk2h(f2, f3);
            hv.z = pk2h(f4, f5); hv.w = pk2h(f6, f7);
            unsigned c = (unsigned)((kq * 2 + j) * 16) ^ lmsk;
            *(uint4*)(bH + c) = hv;
        }
    };

    // warp tiling: 4x4 warps; warp tile 32 rows x 32 cols
    const int wm = (wid & 3) * 32;
    const int wn = (wid >> 2) * 32;
    const int ai = lane & 7;
    const int ag = lane >> 3;

    unsigned arow[2], amsk[2];
#pragma unroll
    for (int mt = 0; mt < 2; ++mt) {
        int r = wm + mt * 16 + (ag & 1) * 8 + ai;
        arow[mt] = (unsigned)(r * 128);
        amsk[mt] = (unsigned)((r & 7) << 4);
    }
    const unsigned a_c0 = (unsigned)((ag >> 1) * 16);
    unsigned brow[2], bmsk[2];
#pragma unroll
    for (int ntp = 0; ntp < 2; ++ntp) {
        int r = wn + ntp * 16 + (ag >> 1) * 8 + ai;
        brow[ntp] = (unsigned)(r * 128);
        bmsk[ntp] = (unsigned)((r & 7) << 4);
    }
    const unsigned b_c0 = (unsigned)((ag & 1) * 16);

    auto compute = [&](int s) {
        const unsigned xh_b = sm_u32 + s * TSTG;
        const unsigned wh_b = sm_u32 + OFF_WH + s * TSTG;
#pragma unroll
        for (int kk = 0; kk < 4; ++kk) {
            const unsigned ca  = a_c0 + kk * 32;
            const unsigned cbb = b_c0 + kk * 32;
            unsigned ah[2][4], bh[4][2];
#pragma unroll
            for (int mt = 0; mt < 2; ++mt)
                ldsm4(ah[mt][0], ah[mt][1], ah[mt][2], ah[mt][3],
                      xh_b + arow[mt] + (ca ^ amsk[mt]));
#pragma unroll
            for (int ntp = 0; ntp < 2; ++ntp)
                ldsm4(bh[2 * ntp][0], bh[2 * ntp][1], bh[2 * ntp + 1][0], bh[2 * ntp + 1][1],
                      wh_b + brow[ntp] + (cbb ^ bmsk[ntp]));
#pragma unroll
            for (int nt = 0; nt < 4; ++nt)
#pragma unroll
                for (int mt = 0; mt < 2; ++mt)
                    mma16816(acc[mt][nt], ah[mt], bh[nt]);
        }
    };

    // ---- pipelined main loop (2-stage, R10 structure) ----
    cp_w(0, 0);
    ldx(0);
    stx(0);
    cp_wait0();
    __syncthreads();

    for (int kt = 0; kt < NKT; ++kt) {
        int cur = kt & 1;
        if (kt < NKT - 1) {
            cp_w(kt + 1, 1 - cur);
            ldx(kt + 1);
        }
        compute(cur);
        if (kt < NKT - 1) stx(1 - cur);
        cp_wait0();
        __syncthreads();
    }

    // ---- ||x||^2 reduction (4 partials per row) ----
    xnp[tid] = xn;
    __syncthreads();
    if (tid < BM)
        xns[tid] = xnp[4 * tid] + xnp[4 * tid + 1] + xnp[4 * tid + 2] + xnp[4 * tid + 3];
    __syncthreads();

    // ---- epilogue: d -> si[p][b] ----
    {
        const int lq  = lane >> 2;
        const int lr2 = (lane & 3) * 2;
        float xnv[4];
#pragma unroll
        for (int mt = 0; mt < 2; ++mt) {
            xnv[mt * 2 + 0] = xns[wm + mt * 16 + lq];
            xnv[mt * 2 + 1] = xns[wm + mt * 16 + lq + 8];
        }
#pragma unroll
        for (int nt = 0; nt < 4; ++nt) {
            int cp = wn + nt * 8 + lr2;
            float ws0 = wsq[cp],     ws1 = wsq[cp + 1];
            float ga0 = gam[cp],     ga1 = gam[cp + 1];
            float al0 = alp[cp],     al1 = alp[cp + 1];
#pragma unroll
            for (int mt = 0; mt < 2; ++mt) {
                int r0 = wm + mt * 16 + lq;
                int r1 = r0 + 8;
                const float* a = acc[mt][nt];
                float d00 = xnv[mt * 2]     + ws0 - 2.f * a[0];
                float d01 = xnv[mt * 2]     + ws1 - 2.f * a[1];
                float d10 = xnv[mt * 2 + 1] + ws0 - 2.f * a[2];
                float d11 = xnv[mt * 2 + 1] + ws1 - 2.f * a[3];
                si[cp * SIP + r0]       = al0 * __expf(-ga0 * d00);
                si[(cp + 1) * SIP + r0] = al1 * __expf(-ga1 * d01);
                si[cp * SIP + r1]       = al0 * __expf(-ga0 * d10);
                si[(cp + 1) * SIP + r1] = al1 * __expf(-ga1 * d11);
            }
        }
    }
    __syncthreads();

    // ---- Dempster scan: one thread per batch row ----
    if (tid < BM) {
        const int r = tid;
        float mx = 0.f;
        for (int p = 0; p < P_DIM; ++p) mx = fmaxf(mx, si[p * SIP + r]);
        const float sinv = 1.f / (mx + 1e-4f);

        float s = si[r] * sinv;
        float m[C_DIM];
#pragma unroll
        for (int k = 0; k < C_DIM; ++k) m[k] = us[k * P_DIM + 0] * s;
        float o = 1.f - s;

        for (int p = 1; p < P_DIM; ++p) {
            s = si[p * SIP + r] * sinv;
            float om = 1.f - s;
            float os = o * s;
#pragma unroll
            for (int k = 0; k < C_DIM; ++k) {
                float u = us[k * P_DIM + p];
                float t = fmaf(s, u, om);        // 1 - s + s*u
                m[k] = fmaf(m[k], t, os * u);
            }
            o = 3.f * o * om;                    // c_omega = 3*o1*o2
            if ((p & 7) == 7) {                  // scale-invariant renorm
                float ssum = o;
#pragma unroll
                for (int k = 0; k < C_DIM; ++k) ssum += m[k];
                float rinv = 1.f / ssum;
#pragma unroll
                for (int k = 0; k < C_DIM; ++k) m[k] *= rinv;
                o *= rinv;
            }
        }
        float ssum = o;
#pragma unroll
        for (int k = 0; k < C_DIM; ++k) ssum += m[k];
        float rinv = 1.f / ssum;
        float* op = out + (size_t)(row0 + r) * (C_DIM + 1);
#pragma unroll
        for (int k = 0; k < C_DIM; ++k) op[k] = m[k] * rinv;
        op[C_DIM] = o * rinv;
    }
}

// ---------------- launch ----------------
extern "C" void kernel_launch(void* const* d_in, const int* in_sizes, int n_in,
                              void* d_out, int out_size) {
    const float* x    = (const float*)d_in[0];
    const float* w    = (const float*)d_in[1];
    const float* eta  = (const float*)d_in[2];
    const float* xi   = (const float*)d_in[3];
    const float* beta = (const float*)d_in[4];
    float* out = (float*)d_out;

    ds_precomp<<<144, 256>>>(w, eta, xi, beta);

    cudaFuncSetAttribute(ds_main, cudaFuncAttributeMaxDynamicSharedMemorySize,
                         SMEM_BYTES);
    ds_main<<<B_TOTAL / BM, TPB, SMEM_BYTES>>>(x, out);
}